// round 13
// baseline (speedup 1.0000x reference)
#include <cuda_runtime.h>
#include <cuda_bf16.h>
#include <cstdint>

// ---------------------------------------------------------------------------
// Residual MLP block, sm_103 baseline-PTX path.
// GEMMs: mma.sync.m16n8k16 bf16 (fp32 accum). A tile via cp.async + ldmatrix;
// B (weights) via precomputed fragment image in GMEM (L2-resident), LDG.64
// into mma registers, prefetched one k16-step ahead.
// Block 64x128, warp tile 32x32, 3 CTAs/SM (6 warps/SMSP) for latency cover.
// out = x + W2 @ gelu(W1 @ LN(x) + b1) + b2
// ---------------------------------------------------------------------------

#define ROWS   16384
#define WID    1024
#define BM     64
#define BN     128
#define BK     32
#define NITER  (WID / BK)        // 32
#define STAGES 4
#define ASTRIDE 40               // bf16 per smem row (80B, ldmatrix conflict-free)
#define STAGE_E (BM * ASTRIDE)   // 2560 bf16 = 5120 B (A only)
#define SMEM_BYTES (STAGES * STAGE_E * 2)   // 20480 B -> 3 CTAs = 61.4KB/SM
#define KB_TOT (WID / 16)        // 64 k16-blocks
#define NB_TOT (WID / 8)         // 128 n8-blocks

// scratch (device globals: allocation-free per harness rules)
__device__ __nv_bfloat16 g_ln[ROWS * WID];
__device__ __nv_bfloat16 g_h [ROWS * WID];
__device__ uint2 g_w1f[NB_TOT * KB_TOT * 32];   // W1 fragment image (2 MB)
__device__ uint2 g_w2f[NB_TOT * KB_TOT * 32];   // W2 fragment image (2 MB)

// ---------------------------------------------------------------------------
static __device__ __forceinline__ uint32_t smem_u32(const void* p) {
    uint32_t a;
    asm("{ .reg .u64 t; cvta.to.shared.u64 t, %1; cvt.u32.u64 %0, t; }"
        : "=r"(a) : "l"(p));
    return a;
}

static __device__ __forceinline__ uint32_t pack_bf2(float lo, float hi) {
    __nv_bfloat162 b = __floats2bfloat162_rn(lo, hi);
    return *reinterpret_cast<uint32_t*>(&b);
}

static __device__ __forceinline__ void cp_async16(uint32_t saddr, const void* g) {
    asm volatile("cp.async.cg.shared.global [%0], [%1], 16;"
                 :: "r"(saddr), "l"(g) : "memory");
}
#define CP_COMMIT()  asm volatile("cp.async.commit_group;" ::: "memory")
#define CP_WAIT(N)   asm volatile("cp.async.wait_group %0;" :: "n"(N) : "memory")

static __device__ __forceinline__ void ldsm4(uint32_t& r0, uint32_t& r1,
                                             uint32_t& r2, uint32_t& r3, uint32_t a) {
    asm volatile("ldmatrix.sync.aligned.m8n8.x4.shared.b16 {%0,%1,%2,%3}, [%4];"
                 : "=r"(r0), "=r"(r1), "=r"(r2), "=r"(r3) : "r"(a));
}

static __device__ __forceinline__ void mma_bf16(float& c0, float& c1, float& c2, float& c3,
                                                uint32_t a0, uint32_t a1, uint32_t a2, uint32_t a3,
                                                uint32_t b0, uint32_t b1) {
    asm volatile("mma.sync.aligned.m16n8k16.row.col.f32.bf16.bf16.f32 "
                 "{%0,%1,%2,%3}, {%4,%5,%6,%7}, {%8,%9}, {%0,%1,%2,%3};"
                 : "+f"(c0), "+f"(c1), "+f"(c2), "+f"(c3)
                 : "r"(a0), "r"(a1), "r"(a2), "r"(a3), "r"(b0), "r"(b1));
}

static __device__ __forceinline__ float gelu_exact(float v) {
    return 0.5f * v * (1.0f + erff(v * 0.7071067811865476f));
}

// ---------------------------------------------------------------------------
// Build B fragment image: lane-exact mma.m16n8k16 B operands.
//   n' = nb*8 + lane/4, k' = kb*16 + (lane%4)*2
//   b0 = {B[n'][k'], B[n'][k'+1]},  b1 = {B[n'][k'+8], B[n'][k'+9]}
// ---------------------------------------------------------------------------
__global__ void rwf_kernel(const float* __restrict__ w, uint2* __restrict__ o) {
    int idx  = blockIdx.x * blockDim.x + threadIdx.x;   // nb*64*32 + kb*32 + lane
    int lane = idx & 31;
    int kb   = (idx >> 5) & (KB_TOT - 1);
    int nb   = idx >> 11;
    int n = nb * 8 + (lane >> 2);
    int k = kb * 16 + (lane & 3) * 2;
    const float* wr = w + (size_t)n * WID + k;
    uint2 p;
    p.x = pack_bf2(wr[0], wr[1]);
    p.y = pack_bf2(wr[8], wr[9]);
    o[idx] = p;
}

// ---------------------------------------------------------------------------
__global__ void ln_kernel(const float* __restrict__ x, const float* __restrict__ g,
                          const float* __restrict__ b, __nv_bfloat16* __restrict__ o) {
    int row = blockIdx.x;
    int t   = threadIdx.x;
    int wid = t >> 5, lid = t & 31;
    const float4* xr = reinterpret_cast<const float4*>(x + (size_t)row * WID);
    float4 v0 = xr[t], v1 = xr[t + 128];

    float s = v0.x + v0.y + v0.z + v0.w + v1.x + v1.y + v1.z + v1.w;
    float q = v0.x*v0.x + v0.y*v0.y + v0.z*v0.z + v0.w*v0.w
            + v1.x*v1.x + v1.y*v1.y + v1.z*v1.z + v1.w*v1.w;
    #pragma unroll
    for (int off = 16; off > 0; off >>= 1) {
        s += __shfl_xor_sync(0xffffffffu, s, off);
        q += __shfl_xor_sync(0xffffffffu, q, off);
    }
    __shared__ float rs_[4], rq_[4];
    if (lid == 0) { rs_[wid] = s; rq_[wid] = q; }
    __syncthreads();
    float S  = rs_[0] + rs_[1] + rs_[2] + rs_[3];
    float Q  = rq_[0] + rq_[1] + rq_[2] + rq_[3];
    float mu = S * (1.0f / WID);
    float var = Q * (1.0f / WID) - mu * mu;
    float r  = rsqrtf(var + 1e-5f);

    const float4* gr = reinterpret_cast<const float4*>(g);
    const float4* br = reinterpret_cast<const float4*>(b);
    uint2* orow = reinterpret_cast<uint2*>(o + (size_t)row * WID);

    #pragma unroll
    for (int half = 0; half < 2; half++) {
        float4 vv = half ? v1 : v0;
        float4 gg = half ? gr[t + 128] : gr[t];
        float4 bb = half ? br[t + 128] : br[t];
        float o0 = (vv.x - mu) * r * gg.x + bb.x;
        float o1 = (vv.y - mu) * r * gg.y + bb.y;
        float o2 = (vv.z - mu) * r * gg.z + bb.z;
        float o3 = (vv.w - mu) * r * gg.w + bb.w;
        uint2 p;
        p.x = pack_bf2(o0, o1);
        p.y = pack_bf2(o2, o3);
        orow[t + half * 128] = p;
    }
}

// ---------------------------------------------------------------------------
// GEMM: block 64x128, 8 warps (2m x 4n), warp tile 32x32, bf16 k16 MMA.
// A via smem/ldmatrix, B via fragment-image LDG.64 prefetched 1 step ahead.
// 3 CTAs/SM.
// ---------------------------------------------------------------------------
template <bool DO_GELU>
__global__ void __launch_bounds__(256, 3) gemm_kernel(
    const __nv_bfloat16* __restrict__ A, const uint2* __restrict__ Bf,
    const float* __restrict__ bias, const float* __restrict__ resid,
    void* __restrict__ outp)
{
    extern __shared__ __nv_bfloat16 smem[];

    const int tid    = threadIdx.x;
    const int lane   = tid & 31;
    const int w      = tid >> 5;
    const int warp_m = (w & 1) * 32;
    const int warp_n = (w >> 1) * 32;
    const int m0     = blockIdx.x * BM;
    const int n0     = blockIdx.y * BN;
    const int nbase  = (n0 + warp_n) >> 3;   // first n8-block for this warp

    float c[2][4][4];
    #pragma unroll
    for (int mi = 0; mi < 2; mi++)
        #pragma unroll
        for (int ni = 0; ni < 4; ni++)
            #pragma unroll
            for (int r = 0; r < 4; r++) c[mi][ni][r] = 0.0f;

    // cp.async (A only): 64 rows x 32 bf16 = 256 x 16B chunks / 256 thr = 1.
    const int ld_row  = tid >> 2;
    const int ld_kcol = (tid & 3) * 8;
    auto load_stage = [&](int s, int kt) {
        __nv_bfloat16* st = smem + s * STAGE_E;
        cp_async16(smem_u32(st + ld_row * ASTRIDE + ld_kcol),
                   A + (size_t)(m0 + ld_row) * WID + kt * BK + ld_kcol);
        CP_COMMIT();
    };

    #pragma unroll
    for (int s = 0; s < STAGES - 1; s++) load_stage(s, s);

    // ldmatrix per-lane address components for A
    const int a_row  = lane & 15;
    const int a_koff = (lane >> 4) << 3;
    const uint32_t smem_base = smem_u32(smem);

    // B fragment image, lane-resolved base. index = (nb*KB_TOT + kb)*32 + lane
    const uint2* bbase = Bf + ((size_t)nbase * KB_TOT) * 32 + lane;

    // prefetch kb = 0 into buffer 0
    uint2 bfb[2][4];
    #pragma unroll
    for (int ni = 0; ni < 4; ni++)
        bfb[0][ni] = __ldg(bbase + ((size_t)ni * KB_TOT) * 32);

    for (int it = 0; it < NITER; it++) {
        CP_WAIT(STAGES - 2);
        __syncthreads();

        const int nxt = it + STAGES - 1;
        if (nxt < NITER) load_stage(nxt % STAGES, nxt);

        const int buf = it % STAGES;
        const uint32_t as = smem_base + buf * STAGE_E * 2;

        #pragma unroll
        for (int ks = 0; ks < 2; ks++) {           // k16 steps
            const int cur = ks & 1;
            // prefetch NEXT k16-step's B fragments (wraps harmlessly at end)
            const int kb_n = (it * 2 + ks + 1) & (KB_TOT - 1);
            #pragma unroll
            for (int ni = 0; ni < 4; ni++)
                bfb[cur ^ 1][ni] = __ldg(bbase + ((size_t)ni * KB_TOT + kb_n) * 32);

            const int kbo = ks * 16;
            uint32_t af[2][4];
            #pragma unroll
            for (int mi = 0; mi < 2; mi++) {
                uint32_t addr = as + ((warp_m + mi * 16 + a_row) * ASTRIDE
                                      + kbo + a_koff) * 2;
                ldsm4(af[mi][0], af[mi][1], af[mi][2], af[mi][3], addr);
            }
            #pragma unroll
            for (int mi = 0; mi < 2; mi++)
                #pragma unroll
                for (int ni = 0; ni < 4; ni++)
                    mma_bf16(c[mi][ni][0], c[mi][ni][1], c[mi][ni][2], c[mi][ni][3],
                             af[mi][0], af[mi][1], af[mi][2], af[mi][3],
                             bfb[cur][ni].x, bfb[cur][ni].y);
        }
    }

    // epilogue
    #pragma unroll
    for (int ni = 0; ni < 4; ni++) {
        const int col = n0 + warp_n + ni * 8 + (lane & 3) * 2;
        const float2 bv = *reinterpret_cast<const float2*>(bias + col);
        #pragma unroll
        for (int mi = 0; mi < 2; mi++) {
            const int row = m0 + warp_m + mi * 16 + (lane >> 2);
            #pragma unroll
            for (int h = 0; h < 2; h++) {
                const size_t r = (size_t)(row + h * 8);
                float vx = c[mi][ni][2 * h + 0] + bv.x;
                float vy = c[mi][ni][2 * h + 1] + bv.y;
                if (DO_GELU) {
                    uint32_t bp = pack_bf2(gelu_exact(vx), gelu_exact(vy));
                    *reinterpret_cast<uint32_t*>(
                        (__nv_bfloat16*)outp + r * WID + col) = bp;
                } else {
                    const float2 rx = *reinterpret_cast<const float2*>(resid + r * WID + col);
                    float2 v; v.x = vx + rx.x; v.y = vy + rx.y;
                    *reinterpret_cast<float2*>((float*)outp + r * WID + col) = v;
                }
            }
        }
    }
}

// ---------------------------------------------------------------------------
extern "C" void kernel_launch(void* const* d_in, const int* in_sizes, int n_in,
                              void* d_out, int out_size) {
    const float* x     = (const float*)d_in[0];
    const float* gamma = (const float*)d_in[1];
    const float* beta  = (const float*)d_in[2];
    const float* w1    = (const float*)d_in[3];
    const float* b1    = (const float*)d_in[4];
    const float* w2    = (const float*)d_in[5];
    const float* b2    = (const float*)d_in[6];
    float* out = (float*)d_out;

    void *p_ln, *p_h, *p_w1f, *p_w2f;
    cudaGetSymbolAddress(&p_ln,  g_ln);
    cudaGetSymbolAddress(&p_h,   g_h);
    cudaGetSymbolAddress(&p_w1f, g_w1f);
    cudaGetSymbolAddress(&p_w2f, g_w2f);

    cudaFuncSetAttribute(gemm_kernel<true>,
                         cudaFuncAttributeMaxDynamicSharedMemorySize, SMEM_BYTES);
    cudaFuncSetAttribute(gemm_kernel<false>,
                         cudaFuncAttributeMaxDynamicSharedMemorySize, SMEM_BYTES);

    rwf_kernel<<<(NB_TOT * KB_TOT * 32) / 256, 256>>>(w1, (uint2*)p_w1f);
    rwf_kernel<<<(NB_TOT * KB_TOT * 32) / 256, 256>>>(w2, (uint2*)p_w2f);
    ln_kernel<<<ROWS, 128>>>(x, gamma, beta, (__nv_bfloat16*)p_ln);

    dim3 grid(ROWS / BM, WID / BN);   // 256 x 8 = 2048 CTAs
    gemm_kernel<true ><<<grid, 256, SMEM_BYTES>>>((const __nv_bfloat16*)p_ln,
                                                  (const uint2*)p_w1f,
                                                  b1, nullptr, p_h);
    gemm_kernel<false><<<grid, 256, SMEM_BYTES>>>((const __nv_bfloat16*)p_h,
                                                  (const uint2*)p_w2f,
                                                  b2, x, out);
}

// round 15
// speedup vs baseline: 1.1532x; 1.1532x over previous
#include <cuda_runtime.h>
#include <cuda_bf16.h>
#include <cstdint>

// ---------------------------------------------------------------------------
// Residual MLP block, sm_103 baseline-PTX path.
// GEMMs: mma.sync.m16n8k16 bf16 (fp32 accum). A tile via cp.async + ldmatrix;
// B (weights) via precomputed fragment image in GMEM (L2-resident), LDG.64
// into mma registers, prefetched one k16-step ahead.
// Block 128x128 (R12 winner geometry), BK=64 (16 iters, 4 k16-steps/iter),
// warp tile 64x32, 2 CTAs/SM.
// out = x + W2 @ gelu(W1 @ LN(x) + b1) + b2
// ---------------------------------------------------------------------------

#define ROWS   16384
#define WID    1024
#define BM     128
#define BN     128
#define BK     64
#define NITER  (WID / BK)        // 16
#define STAGES 3
#define ASTRIDE 72               // 64 + 8 pad bf16 (144B row: ldmatrix conflict-free)
#define STAGE_E (BM * ASTRIDE)   // 9216 bf16 = 18432 B (A only)
#define SMEM_BYTES (STAGES * STAGE_E * 2)   // 55296 B -> 2 CTAs = 110.6KB/SM
#define KB_TOT (WID / 16)        // 64 k16-blocks
#define NB_TOT (WID / 8)         // 128 n8-blocks

// scratch (device globals: allocation-free per harness rules)
__device__ __nv_bfloat16 g_ln[ROWS * WID];
__device__ __nv_bfloat16 g_h [ROWS * WID];
__device__ uint2 g_w1f[NB_TOT * KB_TOT * 32];   // W1 fragment image (2 MB)
__device__ uint2 g_w2f[NB_TOT * KB_TOT * 32];   // W2 fragment image (2 MB)

// ---------------------------------------------------------------------------
static __device__ __forceinline__ uint32_t smem_u32(const void* p) {
    uint32_t a;
    asm("{ .reg .u64 t; cvta.to.shared.u64 t, %1; cvt.u32.u64 %0, t; }"
        : "=r"(a) : "l"(p));
    return a;
}

static __device__ __forceinline__ uint32_t pack_bf2(float lo, float hi) {
    __nv_bfloat162 b = __floats2bfloat162_rn(lo, hi);
    return *reinterpret_cast<uint32_t*>(&b);
}

static __device__ __forceinline__ void cp_async16(uint32_t saddr, const void* g) {
    asm volatile("cp.async.cg.shared.global [%0], [%1], 16;"
                 :: "r"(saddr), "l"(g) : "memory");
}
#define CP_COMMIT()  asm volatile("cp.async.commit_group;" ::: "memory")
#define CP_WAIT(N)   asm volatile("cp.async.wait_group %0;" :: "n"(N) : "memory")

static __device__ __forceinline__ void ldsm4(uint32_t& r0, uint32_t& r1,
                                             uint32_t& r2, uint32_t& r3, uint32_t a) {
    asm volatile("ldmatrix.sync.aligned.m8n8.x4.shared.b16 {%0,%1,%2,%3}, [%4];"
                 : "=r"(r0), "=r"(r1), "=r"(r2), "=r"(r3) : "r"(a));
}

static __device__ __forceinline__ void mma_bf16(float& c0, float& c1, float& c2, float& c3,
                                                uint32_t a0, uint32_t a1, uint32_t a2, uint32_t a3,
                                                uint32_t b0, uint32_t b1) {
    asm volatile("mma.sync.aligned.m16n8k16.row.col.f32.bf16.bf16.f32 "
                 "{%0,%1,%2,%3}, {%4,%5,%6,%7}, {%8,%9}, {%0,%1,%2,%3};"
                 : "+f"(c0), "+f"(c1), "+f"(c2), "+f"(c3)
                 : "r"(a0), "r"(a1), "r"(a2), "r"(a3), "r"(b0), "r"(b1));
}

static __device__ __forceinline__ float gelu_exact(float v) {
    return 0.5f * v * (1.0f + erff(v * 0.7071067811865476f));
}

// ---------------------------------------------------------------------------
// Build B fragment image: lane-exact mma.m16n8k16 B operands.
//   n' = nb*8 + lane/4, k' = kb*16 + (lane%4)*2
//   b0 = {B[n'][k'], B[n'][k'+1]},  b1 = {B[n'][k'+8], B[n'][k'+9]}
// ---------------------------------------------------------------------------
__global__ void rwf_kernel(const float* __restrict__ w, uint2* __restrict__ o) {
    int idx  = blockIdx.x * blockDim.x + threadIdx.x;   // nb*64*32 + kb*32 + lane
    int lane = idx & 31;
    int kb   = (idx >> 5) & (KB_TOT - 1);
    int nb   = idx >> 11;
    int n = nb * 8 + (lane >> 2);
    int k = kb * 16 + (lane & 3) * 2;
    const float* wr = w + (size_t)n * WID + k;
    uint2 p;
    p.x = pack_bf2(wr[0], wr[1]);
    p.y = pack_bf2(wr[8], wr[9]);
    o[idx] = p;
}

// ---------------------------------------------------------------------------
__global__ void ln_kernel(const float* __restrict__ x, const float* __restrict__ g,
                          const float* __restrict__ b, __nv_bfloat16* __restrict__ o) {
    int row = blockIdx.x;
    int t   = threadIdx.x;
    int wid = t >> 5, lid = t & 31;
    const float4* xr = reinterpret_cast<const float4*>(x + (size_t)row * WID);
    float4 v0 = xr[t], v1 = xr[t + 128];

    float s = v0.x + v0.y + v0.z + v0.w + v1.x + v1.y + v1.z + v1.w;
    float q = v0.x*v0.x + v0.y*v0.y + v0.z*v0.z + v0.w*v0.w
            + v1.x*v1.x + v1.y*v1.y + v1.z*v1.z + v1.w*v1.w;
    #pragma unroll
    for (int off = 16; off > 0; off >>= 1) {
        s += __shfl_xor_sync(0xffffffffu, s, off);
        q += __shfl_xor_sync(0xffffffffu, q, off);
    }
    __shared__ float rs_[4], rq_[4];
    if (lid == 0) { rs_[wid] = s; rq_[wid] = q; }
    __syncthreads();
    float S  = rs_[0] + rs_[1] + rs_[2] + rs_[3];
    float Q  = rq_[0] + rq_[1] + rq_[2] + rq_[3];
    float mu = S * (1.0f / WID);
    float var = Q * (1.0f / WID) - mu * mu;
    float r  = rsqrtf(var + 1e-5f);

    const float4* gr = reinterpret_cast<const float4*>(g);
    const float4* br = reinterpret_cast<const float4*>(b);
    uint2* orow = reinterpret_cast<uint2*>(o + (size_t)row * WID);

    #pragma unroll
    for (int half = 0; half < 2; half++) {
        float4 vv = half ? v1 : v0;
        float4 gg = half ? gr[t + 128] : gr[t];
        float4 bb = half ? br[t + 128] : br[t];
        float o0 = (vv.x - mu) * r * gg.x + bb.x;
        float o1 = (vv.y - mu) * r * gg.y + bb.y;
        float o2 = (vv.z - mu) * r * gg.z + bb.z;
        float o3 = (vv.w - mu) * r * gg.w + bb.w;
        uint2 p;
        p.x = pack_bf2(o0, o1);
        p.y = pack_bf2(o2, o3);
        orow[t + half * 128] = p;
    }
}

// ---------------------------------------------------------------------------
// GEMM: block 128x128, 8 warps (2m x 4n), warp tile 64x32, bf16 k16 MMA.
// BK=64: 4 k16-steps per barrier. A via smem/ldmatrix, B via fragment image
// LDG.64 prefetched one k16-step ahead. 2 CTAs/SM.
// ---------------------------------------------------------------------------
template <bool DO_GELU>
__global__ void __launch_bounds__(256, 2) gemm_kernel(
    const __nv_bfloat16* __restrict__ A, const uint2* __restrict__ Bf,
    const float* __restrict__ bias, const float* __restrict__ resid,
    void* __restrict__ outp)
{
    extern __shared__ __nv_bfloat16 smem[];

    const int tid    = threadIdx.x;
    const int lane   = tid & 31;
    const int w      = tid >> 5;
    const int warp_m = (w & 1) * 64;
    const int warp_n = (w >> 1) * 32;
    const int m0     = blockIdx.x * BM;
    const int n0     = blockIdx.y * BN;
    const int nbase  = (n0 + warp_n) >> 3;   // first n8-block for this warp

    float c[4][4][4];
    #pragma unroll
    for (int mi = 0; mi < 4; mi++)
        #pragma unroll
        for (int ni = 0; ni < 4; ni++)
            #pragma unroll
            for (int r = 0; r < 4; r++) c[mi][ni][r] = 0.0f;

    // cp.async (A only): 128 rows x 64 bf16 (128B) = 8 chunks/row ->
    // 1024 chunks / 256 thr = 4 per thread.
    auto load_stage = [&](int s, int kt) {
        const int k0 = kt * BK;
        __nv_bfloat16* st = smem + s * STAGE_E;
        #pragma unroll
        for (int i = 0; i < 4; i++) {
            const int ch   = tid + i * 256;
            const int row  = ch >> 3;
            const int kcol = (ch & 7) * 8;
            cp_async16(smem_u32(st + row * ASTRIDE + kcol),
                       A + (size_t)(m0 + row) * WID + k0 + kcol);
        }
        CP_COMMIT();
    };

    #pragma unroll
    for (int s = 0; s < STAGES - 1; s++) load_stage(s, s);

    // ldmatrix per-lane address components for A
    const int a_row  = lane & 15;
    const int a_koff = (lane >> 4) << 3;
    const uint32_t smem_base = smem_u32(smem);

    // B fragment image, lane-resolved base. index = (nb*KB_TOT + kb)*32 + lane
    const uint2* bbase = Bf + ((size_t)nbase * KB_TOT) * 32 + lane;

    // prefetch kb = 0 into buffer 0
    uint2 bfb[2][4];
    #pragma unroll
    for (int ni = 0; ni < 4; ni++)
        bfb[0][ni] = __ldg(bbase + ((size_t)ni * KB_TOT) * 32);

    for (int it = 0; it < NITER; it++) {
        CP_WAIT(STAGES - 2);
        __syncthreads();

        const int nxt = it + STAGES - 1;
        if (nxt < NITER) load_stage(nxt % STAGES, nxt);

        const int buf = it % STAGES;
        const uint32_t as = smem_base + buf * STAGE_E * 2;

        #pragma unroll
        for (int ks = 0; ks < 4; ks++) {           // 4 k16-steps per stage
            const int cur = ks & 1;
            // prefetch NEXT k16-step's B fragments (wraps harmlessly at end)
            const int kb_n = (it * 4 + ks + 1) & (KB_TOT - 1);
            #pragma unroll
            for (int ni = 0; ni < 4; ni++)
                bfb[cur ^ 1][ni] = __ldg(bbase + ((size_t)ni * KB_TOT + kb_n) * 32);

            const int kbo = ks * 16;
            uint32_t af[4][4];
            #pragma unroll
            for (int mi = 0; mi < 4; mi++) {
                uint32_t addr = as + ((warp_m + mi * 16 + a_row) * ASTRIDE
                                      + kbo + a_koff) * 2;
                ldsm4(af[mi][0], af[mi][1], af[mi][2], af[mi][3], addr);
            }
            #pragma unroll
            for (int mi = 0; mi < 4; mi++)
                #pragma unroll
                for (int ni = 0; ni < 4; ni++)
                    mma_bf16(c[mi][ni][0], c[mi][ni][1], c[mi][ni][2], c[mi][ni][3],
                             af[mi][0], af[mi][1], af[mi][2], af[mi][3],
                             bfb[cur][ni].x, bfb[cur][ni].y);
        }
    }

    // epilogue
    #pragma unroll
    for (int ni = 0; ni < 4; ni++) {
        const int col = n0 + warp_n + ni * 8 + (lane & 3) * 2;
        const float2 bv = *reinterpret_cast<const float2*>(bias + col);
        #pragma unroll
        for (int mi = 0; mi < 4; mi++) {
            const int row = m0 + warp_m + mi * 16 + (lane >> 2);
            #pragma unroll
            for (int h = 0; h < 2; h++) {
                const size_t r = (size_t)(row + h * 8);
                float vx = c[mi][ni][2 * h + 0] + bv.x;
                float vy = c[mi][ni][2 * h + 1] + bv.y;
                if (DO_GELU) {
                    uint32_t bp = pack_bf2(gelu_exact(vx), gelu_exact(vy));
                    *reinterpret_cast<uint32_t*>(
                        (__nv_bfloat16*)outp + r * WID + col) = bp;
                } else {
                    const float2 rx = *reinterpret_cast<const float2*>(resid + r * WID + col);
                    float2 v; v.x = vx + rx.x; v.y = vy + rx.y;
                    *reinterpret_cast<float2*>((float*)outp + r * WID + col) = v;
                }
            }
        }
    }
}

// ---------------------------------------------------------------------------
extern "C" void kernel_launch(void* const* d_in, const int* in_sizes, int n_in,
                              void* d_out, int out_size) {
    const float* x     = (const float*)d_in[0];
    const float* gamma = (const float*)d_in[1];
    const float* beta  = (const float*)d_in[2];
    const float* w1    = (const float*)d_in[3];
    const float* b1    = (const float*)d_in[4];
    const float* w2    = (const float*)d_in[5];
    const float* b2    = (const float*)d_in[6];
    float* out = (float*)d_out;

    void *p_ln, *p_h, *p_w1f, *p_w2f;
    cudaGetSymbolAddress(&p_ln,  g_ln);
    cudaGetSymbolAddress(&p_h,   g_h);
    cudaGetSymbolAddress(&p_w1f, g_w1f);
    cudaGetSymbolAddress(&p_w2f, g_w2f);

    cudaFuncSetAttribute(gemm_kernel<true>,
                         cudaFuncAttributeMaxDynamicSharedMemorySize, SMEM_BYTES);
    cudaFuncSetAttribute(gemm_kernel<false>,
                         cudaFuncAttributeMaxDynamicSharedMemorySize, SMEM_BYTES);

    rwf_kernel<<<(NB_TOT * KB_TOT * 32) / 256, 256>>>(w1, (uint2*)p_w1f);
    rwf_kernel<<<(NB_TOT * KB_TOT * 32) / 256, 256>>>(w2, (uint2*)p_w2f);
    ln_kernel<<<ROWS, 128>>>(x, gamma, beta, (__nv_bfloat16*)p_ln);

    dim3 grid(ROWS / BM, WID / BN);   // 128 x 8 = 1024 CTAs
    gemm_kernel<true ><<<grid, 256, SMEM_BYTES>>>((const __nv_bfloat16*)p_ln,
                                                  (const uint2*)p_w1f,
                                                  b1, nullptr, p_h);
    gemm_kernel<false><<<grid, 256, SMEM_BYTES>>>((const __nv_bfloat16*)p_h,
                                                  (const uint2*)p_w2f,
                                                  b2, x, out);
}